// round 4
// baseline (speedup 1.0000x reference)
#include <cuda_runtime.h>
#include <cstdint>

#define Bn 8192
#define Fn 4096
#define Kn 64
#define MT 64            // rows per CTA -> 128 CTAs
#define KC 32            // F-depth per stage
#define NT 256
#define STAGES 6
#define NTILES (Fn / KC) // 128

#define ROWB 144         // row stride bytes (36 floats = 32 + 4 pad)

// ---- smem layout (bytes) ----
#define SM_S      0                     // s table: 4096 f32 = 16384
#define SM_XSQ    16384                 // 64 f32 = 256
#define SM_RED    16640                 // 4 x 64 f32 = 1024
#define SM_TILES  17664
#define SLOT_X    0                     // 64 x 144 = 9216
#define SLOT_V    9216                  // 64 x 144 = 9216 (raw f32 v^T)
#define SLOT_SZ   18432
#define SMEM_TOTAL (SM_TILES + STAGES * SLOT_SZ)   // 128256

__device__ float d_s[Fn];
__device__ float d_vt[Kn * Fn];    // v^T raw f32  [64][4096]

__device__ __forceinline__ uint32_t smem_u32(const void* p) {
    uint32_t a;
    asm("{ .reg .u64 t; cvta.to.shared.u64 t, %1; cvt.u32.u64 %0, t; }" : "=r"(a) : "l"(p));
    return a;
}
#define CP16(sa, gp) \
    asm volatile("cp.async.cg.shared.global [%0], [%1], 16;" :: "r"(sa), "l"(gp) : "memory")
#define CP_COMMIT() asm volatile("cp.async.commit_group;" ::: "memory")

__device__ __forceinline__ uint32_t to_tf32(float f) {
    uint32_t u;
    asm("cvt.rna.tf32.f32 %0, %1;" : "=r"(u) : "f"(f));
    return u;
}
__device__ __forceinline__ void mma_tf32(float* c, const uint32_t* a,
                                         uint32_t b0, uint32_t b1) {
    asm volatile("mma.sync.aligned.m16n8k8.row.col.f32.tf32.tf32.f32 "
                 "{%0,%1,%2,%3}, {%4,%5,%6,%7}, {%8,%9}, {%0,%1,%2,%3};"
                 : "+f"(c[0]), "+f"(c[1]), "+f"(c[2]), "+f"(c[3])
                 : "r"(a[0]), "r"(a[1]), "r"(a[2]), "r"(a[3]), "r"(b0), "r"(b1));
}

// ================= fused prep kernel: transpose v + s table =================
__global__ void prep_v(const float* __restrict__ v) {
    __shared__ float tile[64][65];
    const int f0 = blockIdx.x * 64;
    const int tid = threadIdx.x;
    for (int i = tid; i < 64 * 64; i += 256) {
        int fr = i >> 6, k = i & 63;
        tile[fr][k] = v[(size_t)(f0 + fr) * Kn + k];
    }
    __syncthreads();
    for (int i = tid; i < 64 * 64; i += 256) {
        int k = i >> 6, fr = i & 63;
        d_vt[(size_t)k * Fn + f0 + fr] = tile[fr][k];
    }
    // s[f] = sum_k v[f][k]^2 : 4 threads per f-row
    const int fr = tid >> 2, q = tid & 3;
    float t = 0.f;
#pragma unroll
    for (int j = 0; j < 16; j++) {
        float val = tile[fr][q * 16 + j];
        t = fmaf(val, val, t);
    }
    t += __shfl_xor_sync(0xffffffffu, t, 1);
    t += __shfl_xor_sync(0xffffffffu, t, 2);
    if (q == 0) d_s[f0 + fr] = t;
}

// ================= main kernel =================
__device__ __forceinline__ void load_stage(const float* __restrict__ x, int row0,
                                           int t, uint32_t sb) {
    const int slot = t % STAGES;
    const int f0 = t * KC;
    const uint32_t base = sb + SM_TILES + slot * SLOT_SZ;
    const int tid = threadIdx.x;
#pragma unroll
    for (int i = 0; i < 2; i++) {
        int id = tid + NT * i;                  // 0..511
        int r = id >> 3, c = id & 7;
        uint32_t off = (uint32_t)(r * ROWB + c * 16);
        CP16(base + SLOT_X + off, x + (size_t)(row0 + r) * Fn + f0 + c * 4);
        CP16(base + SLOT_V + off, d_vt + (size_t)r * Fn + f0 + c * 4);
    }
}

__global__ void __launch_bounds__(NT, 1) fm_kernel(const float* __restrict__ x,
                                                   float* __restrict__ out) {
    extern __shared__ char smem[];
    const uint32_t sb = smem_u32(smem);
    const int tid = threadIdx.x;
    const int warp = tid >> 5, lane = tid & 31;
    const int wm = warp >> 2;        // 0..1  -> M offset 32*wm
    const int wn = warp & 3;         // 0..3  -> N offset 16*wn
    const int lr = lane >> 2, lc = lane & 3;
    const int row0 = blockIdx.x * MT;

    // stage s table
    {
        const float4* sg = (const float4*)d_s;
        float4* ss = (float4*)(smem + SM_S);
        for (int i = tid; i < Fn / 4; i += NT) ss[i] = sg[i];
    }

    // preload stages 0..STAGES-2
    for (int t = 0; t < STAGES - 1; t++) { load_stage(x, row0, t, sb); CP_COMMIT(); }

    float acc[2][2][4];
#pragma unroll
    for (int a = 0; a < 2; a++)
#pragma unroll
        for (int b = 0; b < 2; b++)
#pragma unroll
            for (int c = 0; c < 4; c++) acc[a][b][c] = 0.f;
    float xs[4] = {0.f, 0.f, 0.f, 0.f};

    const uint32_t aoff = (uint32_t)((32 * wm + lr) * ROWB + lc * 4);
    const uint32_t boff = (uint32_t)((16 * wn + lr) * ROWB + lc * 4);
    const bool do_xsq = (wn == 0);

    for (int t = 0; t < NTILES; t++) {
        const int slot = t % STAGES;
        if (t + STAGES - 1 < NTILES) asm volatile("cp.async.wait_group %0;" :: "n"(STAGES - 2) : "memory");
        else                         asm volatile("cp.async.wait_group 0;" ::: "memory");
        __syncthreads();
        if (t + STAGES - 1 < NTILES) { load_stage(x, row0, t + STAGES - 1, sb); CP_COMMIT(); }

        const char* tileb = smem + SM_TILES + slot * SLOT_SZ;
        const char* xb = tileb + SLOT_X;
        const char* vb = tileb + SLOT_V;
        const char* srow = smem + SM_S + (t * KC + lc) * 4;

#pragma unroll
        for (int ks = 0; ks < 4; ks++) {
            float araw[2][4];
            uint32_t ar[2][4];
#pragma unroll
            for (int mt = 0; mt < 2; mt++) {
                const char* ab = xb + aoff + mt * (16 * ROWB) + ks * 32;
                araw[mt][0] = *(const float*)(ab);
                araw[mt][1] = *(const float*)(ab + 8 * ROWB);
                araw[mt][2] = *(const float*)(ab + 16);
                araw[mt][3] = *(const float*)(ab + 8 * ROWB + 16);
                ar[mt][0] = to_tf32(araw[mt][0]);
                ar[mt][1] = to_tf32(araw[mt][1]);
                ar[mt][2] = to_tf32(araw[mt][2]);
                ar[mt][3] = to_tf32(araw[mt][3]);
            }
            // x^2 * s (exact fp32) from the raw A fragments — wn==0 warps only
            if (do_xsq) {
                float s0 = *(const float*)(srow + ks * 32);
                float s1 = *(const float*)(srow + ks * 32 + 16);
#pragma unroll
                for (int mt = 0; mt < 2; mt++) {
                    xs[2 * mt]     = fmaf(araw[mt][0] * araw[mt][0], s0, xs[2 * mt]);
                    xs[2 * mt]     = fmaf(araw[mt][2] * araw[mt][2], s1, xs[2 * mt]);
                    xs[2 * mt + 1] = fmaf(araw[mt][1] * araw[mt][1], s0, xs[2 * mt + 1]);
                    xs[2 * mt + 1] = fmaf(araw[mt][3] * araw[mt][3], s1, xs[2 * mt + 1]);
                }
            }
#pragma unroll
            for (int nt = 0; nt < 2; nt++) {
                const char* bb = vb + boff + nt * (8 * ROWB) + ks * 32;
                float b0 = *(const float*)(bb);
                float b1 = *(const float*)(bb + 16);
                uint32_t h0 = to_tf32(b0), h1 = to_tf32(b1);
                uint32_t l0 = to_tf32(b0 - __uint_as_float(h0));
                uint32_t l1 = to_tf32(b1 - __uint_as_float(h1));
                mma_tf32(acc[0][nt], ar[0], h0, h1);
                mma_tf32(acc[1][nt], ar[1], h0, h1);
                mma_tf32(acc[0][nt], ar[0], l0, l1);
                mma_tf32(acc[1][nt], ar[1], l0, l1);
            }
        }
    }

    // ---- epilogue ----
    float* xsq_s = (float*)(smem + SM_XSQ);
    if (do_xsq) {
#pragma unroll
        for (int i = 0; i < 4; i++) {
            float p = xs[i];
            p += __shfl_xor_sync(0xffffffffu, p, 1);
            p += __shfl_xor_sync(0xffffffffu, p, 2);
            if (lc == 0) xsq_s[32 * wm + 16 * (i >> 1) + 8 * (i & 1) + lr] = p;
        }
    }

    float* red = (float*)(smem + SM_RED);
#pragma unroll
    for (int mt = 0; mt < 2; mt++) {
        float p0 = acc[mt][0][0] * acc[mt][0][0] + acc[mt][0][1] * acc[mt][0][1]
                 + acc[mt][1][0] * acc[mt][1][0] + acc[mt][1][1] * acc[mt][1][1];
        float p1 = acc[mt][0][2] * acc[mt][0][2] + acc[mt][0][3] * acc[mt][0][3]
                 + acc[mt][1][2] * acc[mt][1][2] + acc[mt][1][3] * acc[mt][1][3];
        p0 += __shfl_xor_sync(0xffffffffu, p0, 1);
        p0 += __shfl_xor_sync(0xffffffffu, p0, 2);
        p1 += __shfl_xor_sync(0xffffffffu, p1, 1);
        p1 += __shfl_xor_sync(0xffffffffu, p1, 2);
        if (lc == 0) {
            int r = 32 * wm + 16 * mt + lr;
            red[wn * 64 + r] = p0;
            red[wn * 64 + r + 8] = p1;
        }
    }
    __syncthreads();

    if (tid < MT) {
        float tot = red[tid] + red[64 + tid] + red[128 + tid] + red[192 + tid];
        out[row0 + tid] = 0.5f * (tot - xsq_s[tid]);
    }
}

extern "C" void kernel_launch(void* const* d_in, const int* in_sizes, int n_in,
                              void* d_out, int out_size) {
    const float* x = (const float*)d_in[0];   // [8192, 4096]
    const float* v = (const float*)d_in[1];   // [4096, 64]
    float* out = (float*)d_out;               // [8192, 1]

    cudaFuncSetAttribute(fm_kernel, cudaFuncAttributeMaxDynamicSharedMemorySize, SMEM_TOTAL);
    prep_v<<<Fn / 64, 256>>>(v);
    fm_kernel<<<Bn / MT, NT, SMEM_TOTAL>>>(x, out);
}

// round 5
// speedup vs baseline: 1.0237x; 1.0237x over previous
#include <cuda_runtime.h>
#include <cstdint>

#define Bn 8192
#define Fn 4096
#define Kn 64
#define MT 64            // rows per CTA -> 128 CTAs
#define KC 32            // F-depth per stage
#define NT 512           // 16 warps: 4M x 4N
#define STAGES 7
#define NTILES (Fn / KC) // 128

#define ROWB 144         // row stride bytes (36 floats = 32 + 4 pad)

// ---- smem layout (bytes) ----
#define SM_S      0                     // s table: 4096 f32 = 16384
#define SM_XSQ    16384                 // 64 f32 = 256
#define SM_RED    16640                 // 4 x 64 f32 = 1024
#define SM_TILES  17664
#define SLOT_X    0                     // 64 x 144 = 9216
#define SLOT_VH   9216
#define SLOT_VL   18432
#define SLOT_SZ   27648
#define SMEM_TOTAL (SM_TILES + STAGES * SLOT_SZ)   // 211200

__device__ float d_s[Fn];
__device__ float d_vth[Kn * Fn];   // v^T hi, tf32-exact  [64][4096]
__device__ float d_vtl[Kn * Fn];   // v^T lo, tf32-exact

__device__ __forceinline__ uint32_t smem_u32(const void* p) {
    uint32_t a;
    asm("{ .reg .u64 t; cvta.to.shared.u64 t, %1; cvt.u32.u64 %0, t; }" : "=r"(a) : "l"(p));
    return a;
}
#define CP16(sa, gp) \
    asm volatile("cp.async.cg.shared.global [%0], [%1], 16;" :: "r"(sa), "l"(gp) : "memory")
#define CP_COMMIT() asm volatile("cp.async.commit_group;" ::: "memory")

__device__ __forceinline__ uint32_t to_tf32(float f) {
    uint32_t u;
    asm("cvt.rna.tf32.f32 %0, %1;" : "=r"(u) : "f"(f));
    return u;
}
__device__ __forceinline__ void mma_tf32(float* c, const uint32_t* a,
                                         uint32_t b0, uint32_t b1) {
    asm volatile("mma.sync.aligned.m16n8k8.row.col.f32.tf32.tf32.f32 "
                 "{%0,%1,%2,%3}, {%4,%5,%6,%7}, {%8,%9}, {%0,%1,%2,%3};"
                 : "+f"(c[0]), "+f"(c[1]), "+f"(c[2]), "+f"(c[3])
                 : "r"(a[0]), "r"(a[1]), "r"(a[2]), "r"(a[3]), "r"(b0), "r"(b1));
}

// ============ fused prep: transpose v into tf32 hi/lo + s table ============
__global__ void prep_v(const float* __restrict__ v) {
    __shared__ float tile[64][65];
    const int f0 = blockIdx.x * 64;
    const int tid = threadIdx.x;
    for (int i = tid; i < 64 * 64; i += 256) {
        int fr = i >> 6, k = i & 63;
        tile[fr][k] = v[(size_t)(f0 + fr) * Kn + k];
    }
    __syncthreads();
    for (int i = tid; i < 64 * 64; i += 256) {
        int k = i >> 6, fr = i & 63;
        float val = tile[fr][k];
        float hi = __uint_as_float(to_tf32(val));
        float lo = __uint_as_float(to_tf32(val - hi));
        d_vth[(size_t)k * Fn + f0 + fr] = hi;
        d_vtl[(size_t)k * Fn + f0 + fr] = lo;
    }
    // s[f] = sum_k v[f][k]^2 : 4 threads per f-row
    const int fr = tid >> 2, q = tid & 3;
    float t = 0.f;
#pragma unroll
    for (int j = 0; j < 16; j++) {
        float val = tile[fr][q * 16 + j];
        t = fmaf(val, val, t);
    }
    t += __shfl_xor_sync(0xffffffffu, t, 1);
    t += __shfl_xor_sync(0xffffffffu, t, 2);
    if (q == 0) d_s[f0 + fr] = t;
}

// ================= main kernel =================
__device__ __forceinline__ void load_stage(const float* __restrict__ x, int row0,
                                           int t, uint32_t sb) {
    const int slot = t % STAGES;
    const int f0 = t * KC;
    const uint32_t base = sb + SM_TILES + slot * SLOT_SZ;
    const int tid = threadIdx.x;
    const int r = tid >> 3, c = tid & 7;
    const uint32_t off = (uint32_t)(r * ROWB + c * 16);
    CP16(base + SLOT_X + off, x + (size_t)(row0 + r) * Fn + f0 + c * 4);
    CP16(base + SLOT_VH + off, d_vth + (size_t)r * Fn + f0 + c * 4);
    CP16(base + SLOT_VL + off, d_vtl + (size_t)r * Fn + f0 + c * 4);
}

__global__ void __launch_bounds__(NT, 1) fm_kernel(const float* __restrict__ x,
                                                   float* __restrict__ out) {
    extern __shared__ char smem[];
    const uint32_t sb = smem_u32(smem);
    const int tid = threadIdx.x;
    const int warp = tid >> 5, lane = tid & 31;
    const int wm = warp >> 2;        // 0..3  -> M offset 16*wm
    const int wn = warp & 3;         // 0..3  -> N offset 16*wn
    const int lr = lane >> 2, lc = lane & 3;
    const int row0 = blockIdx.x * MT;

    // stage s table
    {
        const float4* sg = (const float4*)d_s;
        float4* ss = (float4*)(smem + SM_S);
        for (int i = tid; i < Fn / 4; i += NT) ss[i] = sg[i];
    }

    // preload stages 0..STAGES-2
    for (int t = 0; t < STAGES - 1; t++) { load_stage(x, row0, t, sb); CP_COMMIT(); }

    float acc[2][4];
#pragma unroll
    for (int b = 0; b < 2; b++)
#pragma unroll
        for (int c = 0; c < 4; c++) acc[b][c] = 0.f;
    float xs[2] = {0.f, 0.f};

    const uint32_t aoff = (uint32_t)((16 * wm + lr) * ROWB + lc * 4);
    const uint32_t boff = (uint32_t)((16 * wn + lr) * ROWB + lc * 4);
    const bool do_xsq = (wn == 0);

    for (int t = 0; t < NTILES; t++) {
        const int slot = t % STAGES;
        if (t + STAGES - 1 < NTILES) asm volatile("cp.async.wait_group %0;" :: "n"(STAGES - 2) : "memory");
        else                         asm volatile("cp.async.wait_group 0;" ::: "memory");
        __syncthreads();
        if (t + STAGES - 1 < NTILES) { load_stage(x, row0, t + STAGES - 1, sb); CP_COMMIT(); }

        const char* tileb = smem + SM_TILES + slot * SLOT_SZ;
        const char* xb  = tileb + SLOT_X;
        const char* vhb = tileb + SLOT_VH;
        const char* vlb = tileb + SLOT_VL;
        const char* srow = smem + SM_S + (t * KC + lc) * 4;

#pragma unroll
        for (int ks = 0; ks < 4; ks++) {
            float araw[4];
            uint32_t ar[4];
            const char* ab = xb + aoff + ks * 32;
            araw[0] = *(const float*)(ab);
            araw[1] = *(const float*)(ab + 8 * ROWB);
            araw[2] = *(const float*)(ab + 16);
            araw[3] = *(const float*)(ab + 8 * ROWB + 16);
            ar[0] = to_tf32(araw[0]);
            ar[1] = to_tf32(araw[1]);
            ar[2] = to_tf32(araw[2]);
            ar[3] = to_tf32(araw[3]);

            if (do_xsq) {
                float s0 = *(const float*)(srow + ks * 32);
                float s1 = *(const float*)(srow + ks * 32 + 16);
                xs[0] = fmaf(araw[0] * araw[0], s0, xs[0]);
                xs[0] = fmaf(araw[2] * araw[2], s1, xs[0]);
                xs[1] = fmaf(araw[1] * araw[1], s0, xs[1]);
                xs[1] = fmaf(araw[3] * araw[3], s1, xs[1]);
            }
#pragma unroll
            for (int nt = 0; nt < 2; nt++) {
                const char* bh = vhb + boff + nt * (8 * ROWB) + ks * 32;
                uint32_t h0 = *(const uint32_t*)(bh);
                uint32_t h1 = *(const uint32_t*)(bh + 16);
                mma_tf32(acc[nt], ar, h0, h1);
                const char* bl = vlb + boff + nt * (8 * ROWB) + ks * 32;
                uint32_t l0 = *(const uint32_t*)(bl);
                uint32_t l1 = *(const uint32_t*)(bl + 16);
                mma_tf32(acc[nt], ar, l0, l1);
            }
        }
    }

    // ---- epilogue ----
    float* xsq_s = (float*)(smem + SM_XSQ);
    if (do_xsq) {
#pragma unroll
        for (int i = 0; i < 2; i++) {
            float p = xs[i];
            p += __shfl_xor_sync(0xffffffffu, p, 1);
            p += __shfl_xor_sync(0xffffffffu, p, 2);
            if (lc == 0) xsq_s[16 * wm + 8 * i + lr] = p;
        }
    }

    float* red = (float*)(smem + SM_RED);
    {
        float p0 = acc[0][0] * acc[0][0] + acc[0][1] * acc[0][1]
                 + acc[1][0] * acc[1][0] + acc[1][1] * acc[1][1];
        float p1 = acc[0][2] * acc[0][2] + acc[0][3] * acc[0][3]
                 + acc[1][2] * acc[1][2] + acc[1][3] * acc[1][3];
        p0 += __shfl_xor_sync(0xffffffffu, p0, 1);
        p0 += __shfl_xor_sync(0xffffffffu, p0, 2);
        p1 += __shfl_xor_sync(0xffffffffu, p1, 1);
        p1 += __shfl_xor_sync(0xffffffffu, p1, 2);
        if (lc == 0) {
            int r = 16 * wm + lr;
            red[wn * 64 + r] = p0;
            red[wn * 64 + r + 8] = p1;
        }
    }
    __syncthreads();

    if (tid < MT) {
        float tot = red[tid] + red[64 + tid] + red[128 + tid] + red[192 + tid];
        out[row0 + tid] = 0.5f * (tot - xsq_s[tid]);
    }
}

extern "C" void kernel_launch(void* const* d_in, const int* in_sizes, int n_in,
                              void* d_out, int out_size) {
    const float* x = (const float*)d_in[0];   // [8192, 4096]
    const float* v = (const float*)d_in[1];   // [4096, 64]
    float* out = (float*)d_out;               // [8192, 1]

    cudaFuncSetAttribute(fm_kernel, cudaFuncAttributeMaxDynamicSharedMemorySize, SMEM_TOTAL);
    prep_v<<<Fn / 64, 256>>>(v);
    fm_kernel<<<Bn / MT, NT, SMEM_TOTAL>>>(x, out);
}